// round 10
// baseline (speedup 1.0000x reference)
#include <cuda_runtime.h>
#include <cstdint>
#include <cstddef>

// EncoderSelfAttention, tf32 mma.sync pipeline (sm_103-safe: no tcgen05).
// B=2, C=512, N=4096.  All GEMMs K-major SS:  D[M,N] = A[M,:K] . B[N,:K]^T
//   Xt = rne(X^T)                       [n,c]
//   Qt = rne(s*(Xt.Wq^T + bq))          [n,c]
//   Kt = rne(Xt.Wk^T + bk)              [n,c]
//   Vc = rne(Wv.Xt^T + bv)              [c,n]
//   S  = Qt.Kt^T ; P = rne(softmax(S))  [n,m]
//   Ot = rne(P.Vc^T)                    [n,c]
//   y  = Wo.Ot^T + bo                   [c,n]

static constexpr int BDIM = 2, CDIM = 512, NTOK = 4096;
static constexpr long long CN = (long long)CDIM * NTOK;
static constexpr long long NN = (long long)NTOK * NTOK;

__device__ float g_xt[BDIM * NTOK * CDIM];
__device__ float g_q [BDIM * NTOK * CDIM];
__device__ float g_k [BDIM * NTOK * CDIM];
__device__ float g_vc[BDIM * CDIM * NTOK];
__device__ float g_o [BDIM * NTOK * CDIM];
__device__ float g_s [BDIM * NN];
__device__ float g_w [4][CDIM * CDIM];

// ---------------------------------------------------------------- helpers
__device__ __forceinline__ float rne_tf32(float x) {
    float r; asm("cvt.rna.tf32.f32 %0, %1;" : "=f"(r) : "f"(x)); return r;
}
__device__ __forceinline__ uint32_t smem_u32(const void* p) {
    uint32_t a;
    asm("{ .reg .u64 t; cvta.to.shared.u64 t, %1; cvt.u32.u64 %0, t; }" : "=r"(a) : "l"(p));
    return a;
}
#define CP_COMMIT() asm volatile("cp.async.commit_group;" ::: "memory")
#define CP_WAIT(n)  asm volatile("cp.async.wait_group %0;" :: "n"(n) : "memory")
__device__ __forceinline__ void cp16(uint32_t dst, const void* src) {
    asm volatile("cp.async.cg.shared.global [%0], [%1], 16;" :: "r"(dst), "l"(src) : "memory");
}
// D += A(16x8) * B(8x8)^T, tf32. Fragment k-slots {c,c+4} hold original k {2c,2c+1},
// applied identically to A and B (shared k-permutation is GEMM-invariant).
__device__ __forceinline__ void mma16n8k8(float* d, float2 a_lo, float2 a_hi, float2 b) {
    asm volatile(
        "mma.sync.aligned.m16n8k8.row.col.f32.tf32.tf32.f32 "
        "{%0,%1,%2,%3},{%4,%5,%6,%7},{%8,%9},{%0,%1,%2,%3};"
        : "+f"(d[0]), "+f"(d[1]), "+f"(d[2]), "+f"(d[3])
        : "r"(__float_as_uint(a_lo.x)), "r"(__float_as_uint(a_hi.x)),
          "r"(__float_as_uint(a_lo.y)), "r"(__float_as_uint(a_hi.y)),
          "r"(__float_as_uint(b.x)),  "r"(__float_as_uint(b.y)));
}

// ---------------------------------------------------------------- GEMM
// CTA tile 128(M) x 256(N), BK=32. 8 warps = 2(M) x 4(N), warp tile 64x64.
// Smem rows: 32 floats (128B); 16B chunks XOR-swizzled by (row&7). Fragment
// addr over ks advances by pure XOR (ks<<5). Fragments double-buffered in
// registers (prefetch ks+1 during ks MMAs); cp.async addresses hoisted.
static constexpr int STAGES = 4;
static constexpr int A_BY = 128 * 32 * 4;           // 16 KB
static constexpr int B_BY = 256 * 32 * 4;           // 32 KB
static constexpr int STG_BY = A_BY + B_BY;          // 48 KB
static constexpr int SMEM_TOTAL = STAGES * STG_BY;  // 192 KB

__global__ __launch_bounds__(256, 1)
void gemm_mma(const float* __restrict__ A, const float* __restrict__ B,
              float* __restrict__ C, int M, int N, int K,
              long long sA, long long sB, long long sC,
              const float* __restrict__ bias, int bias_mode,  // 0 none, 1 col, 2 row
              float alpha, int do_rne)
{
    extern __shared__ char smem[];
    const uint32_t sb = smem_u32(smem);
    const int tid = threadIdx.x, wid = tid >> 5, lane = tid & 31;
    const int wm = wid >> 2, wn = wid & 3;      // warp grid 2(M) x 4(N)
    const int q = lane & 3, rg = lane >> 2;     // quad col, row-in-group
    const int q1 = q >> 1, q0 = q & 1;
    const int bn = blockIdx.x, bm = blockIdx.y;

    A += (size_t)blockIdx.z * sA;
    B += (size_t)blockIdx.z * sB;
    C += (size_t)blockIdx.z * sC;
    const int lda = K, ldb = K, ldc = N;

    float acc[4][8][4];
#pragma unroll
    for (int i = 0; i < 4; ++i)
#pragma unroll
        for (int j = 0; j < 8; ++j)
#pragma unroll
            for (int e = 0; e < 4; ++e) acc[i][j][e] = 0.f;

    // Fragment base byte offsets (ks = 0). Over ks: addr ^ (ks<<5).
    uint32_t aOff[4][2], bOff[8];
#pragma unroll
    for (int i2 = 0; i2 < 4; ++i2)
#pragma unroll
        for (int h = 0; h < 2; ++h) {
            const int r = wm * 64 + i2 * 16 + rg + h * 8;
            aOff[i2][h] = r * 128 + (((q1 ^ (r & 7))) << 4) + (q0 << 3);
        }
#pragma unroll
    for (int j2 = 0; j2 < 8; ++j2) {
        const int r = wn * 64 + j2 * 8 + rg;
        bOff[j2] = A_BY + r * 128 + (((q1 ^ (r & 7))) << 4) + (q0 << 3);
    }

    // Hoisted cp.async addressing: per-thread smem offsets + gmem element offsets.
    uint32_t sCpA[4], sCpB[8], gCpA[4], gCpB[8];
#pragma unroll
    for (int t = 0; t < 4; ++t) {
        const int id = tid + t * 256, r = id >> 3, ci = id & 7;
        sCpA[t] = r * 128 + ((ci ^ (r & 7)) << 4);
        gCpA[t] = (uint32_t)((bm * 128 + r) * lda + ci * 4);
    }
#pragma unroll
    for (int t = 0; t < 8; ++t) {
        const int id = tid + t * 256, r = id >> 3, ci = id & 7;
        sCpB[t] = A_BY + r * 128 + ((ci ^ (r & 7)) << 4);
        gCpB[t] = (uint32_t)((bn * 256 + r) * ldb + ci * 4);
    }

    auto load_stage = [&](int st, int k0) {
        const uint32_t base = sb + st * STG_BY;
#pragma unroll
        for (int t = 0; t < 4; ++t) cp16(base + sCpA[t], A + gCpA[t] + k0);
#pragma unroll
        for (int t = 0; t < 8; ++t) cp16(base + sCpB[t], B + gCpB[t] + k0);
        CP_COMMIT();
    };

    const int nc = K / 32;
    load_stage(0, 0);
    load_stage(1, 32);
    load_stage(2, 64);

    float2 afr[2][4][2], bfr[2][8];
    auto ldfrag = [&](uint32_t stg, int ksIdx, int buf) {
        const uint32_t kx = (uint32_t)ksIdx << 5;
#pragma unroll
        for (int i2 = 0; i2 < 4; ++i2) {
            afr[buf][i2][0] = *(const float2*)&smem[(stg + aOff[i2][0]) ^ kx];
            afr[buf][i2][1] = *(const float2*)&smem[(stg + aOff[i2][1]) ^ kx];
        }
#pragma unroll
        for (int j2 = 0; j2 < 8; ++j2)
            bfr[buf][j2] = *(const float2*)&smem[(stg + bOff[j2]) ^ kx];
    };

    for (int i = 0; i < nc; ++i) {
        CP_WAIT(2);
        __syncthreads();           // stage i ready; slot (i+3)&3 consumed at iter i-1
        if (i + 3 < nc) load_stage((i + 3) & 3, (i + 3) * 32);
        else CP_COMMIT();          // keep group counts aligned

        const uint32_t stg = (uint32_t)(i & 3) * STG_BY;
        ldfrag(stg, 0, 0);
#pragma unroll
        for (int ks = 0; ks < 4; ++ks) {
            const int cur = ks & 1;
            if (ks < 3) ldfrag(stg, ks + 1, cur ^ 1);   // prefetch next k-step
#pragma unroll
            for (int i2 = 0; i2 < 4; ++i2)
#pragma unroll
                for (int j2 = 0; j2 < 8; ++j2)
                    mma16n8k8(acc[i2][j2], afr[cur][i2][0], afr[cur][i2][1], bfr[cur][j2]);
        }
    }

    // Epilogue: c0,c1 -> (row, col..col+1); c2,c3 -> (row+8, col..col+1)
#pragma unroll
    for (int i2 = 0; i2 < 4; ++i2) {
#pragma unroll
        for (int j2 = 0; j2 < 8; ++j2) {
            const int row = bm * 128 + wm * 64 + i2 * 16 + rg;
            const int col = bn * 256 + wn * 64 + j2 * 8 + 2 * q;
            float b0 = 0.f, b1 = 0.f, b2 = 0.f, b3 = 0.f;
            if (bias_mode == 1) { b0 = bias[col]; b1 = bias[col + 1]; b2 = b0; b3 = b1; }
            else if (bias_mode == 2) { b0 = b1 = bias[row]; b2 = b3 = bias[row + 8]; }
            float v0 = alpha * (acc[i2][j2][0] + b0);
            float v1 = alpha * (acc[i2][j2][1] + b1);
            float v2 = alpha * (acc[i2][j2][2] + b2);
            float v3 = alpha * (acc[i2][j2][3] + b3);
            if (do_rne) { v0 = rne_tf32(v0); v1 = rne_tf32(v1); v2 = rne_tf32(v2); v3 = rne_tf32(v3); }
            *(float2*)&C[(size_t)row * ldc + col]       = make_float2(v0, v1);
            *(float2*)&C[(size_t)(row + 8) * ldc + col] = make_float2(v2, v3);
        }
    }
}

// ------------------------------------------------------- small helper kernels
__global__ __launch_bounds__(256)
void weights_rne(const float* w0, const float* w1, const float* w2, const float* w3,
                 float* o0, float* o1, float* o2, float* o3)
{
    const int i = blockIdx.x * 256 + threadIdx.x;
    o0[i] = rne_tf32(w0[i]); o1[i] = rne_tf32(w1[i]);
    o2[i] = rne_tf32(w2[i]); o3[i] = rne_tf32(w3[i]);
}

// in [R][Cc] -> out [Cc][R] with rne; grid (Cc/32, R/32, batch), block (32,8)
__global__ __launch_bounds__(256)
void transpose_rne(const float* __restrict__ in, float* __restrict__ out,
                   int R, int Cc, long long sIn, long long sOut)
{
    __shared__ float t[32][33];
    in  += (size_t)blockIdx.z * sIn;
    out += (size_t)blockIdx.z * sOut;
    const int tx = threadIdx.x, ty = threadIdx.y;
    const int c0 = blockIdx.x * 32, r0 = blockIdx.y * 32;
#pragma unroll
    for (int j = 0; j < 4; ++j)
        t[ty + j * 8][tx] = in[(size_t)(r0 + ty + j * 8) * Cc + c0 + tx];
    __syncthreads();
#pragma unroll
    for (int j = 0; j < 4; ++j)
        out[(size_t)(c0 + ty + j * 8) * R + r0 + tx] = rne_tf32(t[tx][ty + j * 8]);
}

__global__ __launch_bounds__(256)
void softmax_rne(float* __restrict__ S)
{
    float4* p = (float4*)(S + (size_t)blockIdx.x * NTOK);
    const int tid = threadIdx.x;
    __shared__ float red[8];
    float4 v[4];
    float mx = -3.4e38f;
#pragma unroll
    for (int j = 0; j < 4; ++j) {
        v[j] = p[tid + j * 256];
        mx = fmaxf(mx, fmaxf(fmaxf(v[j].x, v[j].y), fmaxf(v[j].z, v[j].w)));
    }
#pragma unroll
    for (int o = 16; o; o >>= 1) mx = fmaxf(mx, __shfl_xor_sync(~0u, mx, o));
    if ((tid & 31) == 0) red[tid >> 5] = mx;
    __syncthreads();
    mx = red[0];
#pragma unroll
    for (int w = 1; w < 8; ++w) mx = fmaxf(mx, red[w]);
    float sum = 0.f;
#pragma unroll
    for (int j = 0; j < 4; ++j) {
        v[j].x = __expf(v[j].x - mx); v[j].y = __expf(v[j].y - mx);
        v[j].z = __expf(v[j].z - mx); v[j].w = __expf(v[j].w - mx);
        sum += (v[j].x + v[j].y) + (v[j].z + v[j].w);
    }
#pragma unroll
    for (int o = 16; o; o >>= 1) sum += __shfl_xor_sync(~0u, sum, o);
    __syncthreads();
    if ((tid & 31) == 0) red[tid >> 5] = sum;
    __syncthreads();
    float tot = 0.f;
#pragma unroll
    for (int w = 0; w < 8; ++w) tot += red[w];
    const float inv = 1.0f / tot;
#pragma unroll
    for (int j = 0; j < 4; ++j) {
        float4 o4;
        o4.x = rne_tf32(v[j].x * inv); o4.y = rne_tf32(v[j].y * inv);
        o4.z = rne_tf32(v[j].z * inv); o4.w = rne_tf32(v[j].w * inv);
        p[tid + j * 256] = o4;
    }
}

// -------------------------------------------------------------------- launch
extern "C" void kernel_launch(void* const* d_in, const int* in_sizes, int n_in,
                              void* d_out, int out_size)
{
    const float* x  = (const float*)d_in[0];
    const float* wq = (const float*)d_in[1];
    const float* bq = (const float*)d_in[2];
    const float* wk = (const float*)d_in[3];
    const float* bk = (const float*)d_in[4];
    const float* wv = (const float*)d_in[5];
    const float* bv = (const float*)d_in[6];
    const float* wo = (const float*)d_in[7];
    const float* bo = (const float*)d_in[8];
    float* out = (float*)d_out;

    float *xt, *q, *k, *vc, *o, *s, *w;
    cudaGetSymbolAddress((void**)&xt, g_xt);
    cudaGetSymbolAddress((void**)&q,  g_q);
    cudaGetSymbolAddress((void**)&k,  g_k);
    cudaGetSymbolAddress((void**)&vc, g_vc);
    cudaGetSymbolAddress((void**)&o,  g_o);
    cudaGetSymbolAddress((void**)&s,  g_s);
    cudaGetSymbolAddress((void**)&w,  g_w);
    float* wqr = w, *wkr = w + CDIM * CDIM, *wvr = w + 2 * CDIM * CDIM, *wor = w + 3 * CDIM * CDIM;

    cudaFuncSetAttribute(gemm_mma, cudaFuncAttributeMaxDynamicSharedMemorySize, SMEM_TOTAL);

    const float scale = 0.044194173824159216f;  // 1/sqrt(512)

    weights_rne<<<CDIM * CDIM / 256, 256>>>(wq, wk, wv, wo, wqr, wkr, wvr, wor);
    transpose_rne<<<dim3(NTOK / 32, CDIM / 32, BDIM), dim3(32, 8)>>>(x, xt, CDIM, NTOK, CN, CN);

    const dim3 blk(256);
    const dim3 gP(CDIM / 256, NTOK / 128, BDIM);   // (2, 32, 2)  D = [4096, 512]
    const dim3 gS(NTOK / 256, NTOK / 128, BDIM);   // (16, 32, 2) D = [4096, 4096]
    const dim3 gY(NTOK / 256, CDIM / 128, BDIM);   // (16, 4, 2)  D = [512, 4096]

    // Q, K projections: [n, c] layouts
    gemm_mma<<<gP, blk, SMEM_TOTAL>>>(xt, wqr, q, NTOK, CDIM, CDIM, CN, 0, CN, bq, 1, scale, 1);
    gemm_mma<<<gP, blk, SMEM_TOTAL>>>(xt, wkr, k, NTOK, CDIM, CDIM, CN, 0, CN, bk, 1, 1.0f, 1);
    // V projection directly in [c, n] layout: Vc = Wv . Xt^T + bv
    gemm_mma<<<gY, blk, SMEM_TOTAL>>>(wvr, xt, vc, CDIM, NTOK, CDIM, 0, CN, CN, bv, 2, 1.0f, 1);

    // Scores + softmax
    gemm_mma<<<gS, blk, SMEM_TOTAL>>>(q, k, s, NTOK, NTOK, CDIM, CN, CN, NN, nullptr, 0, 1.0f, 0);
    softmax_rne<<<BDIM * NTOK, blk>>>(s);

    // Ot = P . Vc^T  [n, c]
    gemm_mma<<<gP, blk, SMEM_TOTAL>>>(s, vc, o, NTOK, CDIM, NTOK, NN, CN, CN, nullptr, 0, 1.0f, 1);
    // y = Wo . Ot^T + bo  [c, n]
    gemm_mma<<<gY, blk, SMEM_TOTAL>>>(wor, o, out, CDIM, NTOK, CDIM, 0, CN, CN, bo, 2, 1.0f, 0);
}

// round 11
// speedup vs baseline: 1.5807x; 1.5807x over previous
#include <cuda_runtime.h>
#include <cstdint>
#include <cstddef>

// EncoderSelfAttention, tf32 mma.sync pipeline (sm_103-safe: no tcgen05).
// B=2, C=512, N=4096.  All GEMMs K-major SS:  D[M,N] = A[M,:K] . B[N,:K]^T
//   Xt = rne(X^T)                       [n,c]
//   Qt = rne(s*(Xt.Wq^T + bq))          [n,c]
//   Kt = rne(Xt.Wk^T + bk)              [n,c]
//   Vc = rne(Wv.Xt^T + bv)              [c,n]
//   S  = Qt.Kt^T ; P = rne(softmax(S))  [n,m]
//   Ot = rne(P.Vc^T)                    [n,c]
//   y  = Wo.Ot^T + bo                   [c,n]

static constexpr int BDIM = 2, CDIM = 512, NTOK = 4096;
static constexpr long long CN = (long long)CDIM * NTOK;
static constexpr long long NN = (long long)NTOK * NTOK;

__device__ float g_xt[BDIM * NTOK * CDIM];
__device__ float g_q [BDIM * NTOK * CDIM];
__device__ float g_k [BDIM * NTOK * CDIM];
__device__ float g_vc[BDIM * CDIM * NTOK];
__device__ float g_o [BDIM * NTOK * CDIM];
__device__ float g_s [BDIM * NN];
__device__ float g_w [4][CDIM * CDIM];

// ---------------------------------------------------------------- helpers
__device__ __forceinline__ float rne_tf32(float x) {
    float r; asm("cvt.rna.tf32.f32 %0, %1;" : "=f"(r) : "f"(x)); return r;
}
__device__ __forceinline__ uint32_t smem_u32(const void* p) {
    uint32_t a;
    asm("{ .reg .u64 t; cvta.to.shared.u64 t, %1; cvt.u32.u64 %0, t; }" : "=r"(a) : "l"(p));
    return a;
}
#define CP_COMMIT() asm volatile("cp.async.commit_group;" ::: "memory")
#define CP_WAIT(n)  asm volatile("cp.async.wait_group %0;" :: "n"(n) : "memory")
__device__ __forceinline__ void cp16(uint32_t dst, const void* src) {
    asm volatile("cp.async.cg.shared.global [%0], [%1], 16;" :: "r"(dst), "l"(src) : "memory");
}
// D += A(16x8) * B(8x8)^T, tf32.
// Shared k-permutation: MMA k-slot (thread quad q, slot {q, q+4}) holds
// original k = 8q + 4p + 2ks' + {0,1}; identical for A and B -> GEMM-invariant.
__device__ __forceinline__ void mma16n8k8(float* d, float2 a_lo, float2 a_hi, float2 b) {
    asm volatile(
        "mma.sync.aligned.m16n8k8.row.col.f32.tf32.tf32.f32 "
        "{%0,%1,%2,%3},{%4,%5,%6,%7},{%8,%9},{%0,%1,%2,%3};"
        : "+f"(d[0]), "+f"(d[1]), "+f"(d[2]), "+f"(d[3])
        : "r"(__float_as_uint(a_lo.x)), "r"(__float_as_uint(a_hi.x)),
          "r"(__float_as_uint(a_lo.y)), "r"(__float_as_uint(a_hi.y)),
          "r"(__float_as_uint(b.x)),  "r"(__float_as_uint(b.y)));
}

// ---------------------------------------------------------------- GEMM
// CTA tile 128(M) x 256(N), BK=32. 8 warps = 2(M) x 4(N), warp tile 64x64.
// Smem rows: 32 floats (128B); 16B chunks XOR-swizzled by (row&7).
// Each thread's fragment data for a half-chunk p (two k-steps) is ONE LDS.128
// at (base + stg) ^ (p<<4): chunk index 2q+p, swizzled; (2q+1)=(2q)^1.
static constexpr int STAGES = 4;
static constexpr int A_BY = 128 * 32 * 4;           // 16 KB
static constexpr int B_BY = 256 * 32 * 4;           // 32 KB
static constexpr int STG_BY = A_BY + B_BY;          // 48 KB
static constexpr int SMEM_TOTAL = STAGES * STG_BY;  // 192 KB

__global__ __launch_bounds__(256, 1)
void gemm_mma(const float* __restrict__ A, const float* __restrict__ B,
              float* __restrict__ C, int M, int N, int K,
              long long sA, long long sB, long long sC,
              const float* __restrict__ bias, int bias_mode,  // 0 none, 1 col, 2 row
              float alpha, int do_rne)
{
    extern __shared__ char smem[];
    const uint32_t sb = smem_u32(smem);
    const int tid = threadIdx.x, wid = tid >> 5, lane = tid & 31;
    const int wm = wid >> 2, wn = wid & 3;      // warp grid 2(M) x 4(N)
    const int q = lane & 3, rg = lane >> 2;     // quad col, row-in-group
    const int bn = blockIdx.x, bm = blockIdx.y;

    A += (size_t)blockIdx.z * sA;
    B += (size_t)blockIdx.z * sB;
    C += (size_t)blockIdx.z * sC;
    const int lda = K, ldb = K, ldc = N;

    float acc[4][8][4];
#pragma unroll
    for (int i = 0; i < 4; ++i)
#pragma unroll
        for (int j = 0; j < 8; ++j)
#pragma unroll
            for (int e = 0; e < 4; ++e) acc[i][j][e] = 0.f;

    // Fragment base byte offsets (half-chunk p=0: chunk 2q, swizzled by row).
    uint32_t aAdr[4][2], bAdr[8];
#pragma unroll
    for (int i2 = 0; i2 < 4; ++i2)
#pragma unroll
        for (int h = 0; h < 2; ++h) {
            const int r = wm * 64 + i2 * 16 + rg + h * 8;
            aAdr[i2][h] = r * 128 + ((((2 * q) ^ (r & 7))) << 4);
        }
#pragma unroll
    for (int j2 = 0; j2 < 8; ++j2) {
        const int r = wn * 64 + j2 * 8 + rg;
        bAdr[j2] = A_BY + r * 128 + ((((2 * q) ^ (r & 7))) << 4);
    }

    auto load_stage = [&](int st, int k0) {
        const uint32_t base = sb + st * STG_BY;
#pragma unroll
        for (int t = 0; t < 4; ++t) {           // A: 128 rows x 8 chunks
            const int id = tid + t * 256;
            const int r = id >> 3, ci = id & 7;
            cp16(base + r * 128 + ((ci ^ (r & 7)) << 4),
                 A + (size_t)(bm * 128 + r) * lda + k0 + ci * 4);
        }
#pragma unroll
        for (int t = 0; t < 8; ++t) {           // B: 256 rows x 8 chunks
            const int id = tid + t * 256;
            const int r = id >> 3, ci = id & 7;
            cp16(base + A_BY + r * 128 + ((ci ^ (r & 7)) << 4),
                 B + (size_t)(bn * 256 + r) * ldb + k0 + ci * 4);
        }
        CP_COMMIT();
    };

    const int nc = K / 32;
    load_stage(0, 0);
    load_stage(1, 32);
    load_stage(2, 64);

    for (int i = 0; i < nc; ++i) {
        CP_WAIT(2);
        __syncthreads();           // stage i ready; slot (i+3)&3 consumed at iter i-1
        if (i + 3 < nc) load_stage((i + 3) & 3, (i + 3) * 32);
        else CP_COMMIT();          // keep group counts aligned

        const uint32_t stg = (uint32_t)(i & 3) * STG_BY;
#pragma unroll
        for (int p = 0; p < 2; ++p) {           // half-chunk: two k-steps per LDS.128
            const uint32_t px = (uint32_t)p << 4;
            float4 a4[4][2], b4[8];
#pragma unroll
            for (int i2 = 0; i2 < 4; ++i2) {
                a4[i2][0] = *(const float4*)&smem[(stg + aAdr[i2][0]) ^ px];
                a4[i2][1] = *(const float4*)&smem[(stg + aAdr[i2][1]) ^ px];
            }
#pragma unroll
            for (int j2 = 0; j2 < 8; ++j2)
                b4[j2] = *(const float4*)&smem[(stg + bAdr[j2]) ^ px];
#pragma unroll
            for (int ks = 0; ks < 2; ++ks) {    // .xy then .zw
#pragma unroll
                for (int i2 = 0; i2 < 4; ++i2) {
                    const float2 alo = ks ? make_float2(a4[i2][0].z, a4[i2][0].w)
                                          : make_float2(a4[i2][0].x, a4[i2][0].y);
                    const float2 ahi = ks ? make_float2(a4[i2][1].z, a4[i2][1].w)
                                          : make_float2(a4[i2][1].x, a4[i2][1].y);
#pragma unroll
                    for (int j2 = 0; j2 < 8; ++j2) {
                        const float2 bb = ks ? make_float2(b4[j2].z, b4[j2].w)
                                             : make_float2(b4[j2].x, b4[j2].y);
                        mma16n8k8(acc[i2][j2], alo, ahi, bb);
                    }
                }
            }
        }
    }

    // Epilogue: c0,c1 -> (row, col..col+1); c2,c3 -> (row+8, col..col+1)
#pragma unroll
    for (int i2 = 0; i2 < 4; ++i2) {
#pragma unroll
        for (int j2 = 0; j2 < 8; ++j2) {
            const int row = bm * 128 + wm * 64 + i2 * 16 + rg;
            const int col = bn * 256 + wn * 64 + j2 * 8 + 2 * q;
            float b0 = 0.f, b1 = 0.f, b2 = 0.f, b3 = 0.f;
            if (bias_mode == 1) { b0 = bias[col]; b1 = bias[col + 1]; b2 = b0; b3 = b1; }
            else if (bias_mode == 2) { b0 = b1 = bias[row]; b2 = b3 = bias[row + 8]; }
            float v0 = alpha * (acc[i2][j2][0] + b0);
            float v1 = alpha * (acc[i2][j2][1] + b1);
            float v2 = alpha * (acc[i2][j2][2] + b2);
            float v3 = alpha * (acc[i2][j2][3] + b3);
            if (do_rne) { v0 = rne_tf32(v0); v1 = rne_tf32(v1); v2 = rne_tf32(v2); v3 = rne_tf32(v3); }
            *(float2*)&C[(size_t)row * ldc + col]       = make_float2(v0, v1);
            *(float2*)&C[(size_t)(row + 8) * ldc + col] = make_float2(v2, v3);
        }
    }
}

// ------------------------------------------------------- small helper kernels
__global__ __launch_bounds__(256)
void weights_rne(const float* w0, const float* w1, const float* w2, const float* w3,
                 float* o0, float* o1, float* o2, float* o3)
{
    const int i = blockIdx.x * 256 + threadIdx.x;
    o0[i] = rne_tf32(w0[i]); o1[i] = rne_tf32(w1[i]);
    o2[i] = rne_tf32(w2[i]); o3[i] = rne_tf32(w3[i]);
}

// in [R][Cc] -> out [Cc][R] with rne; grid (Cc/32, R/32, batch), block (32,8)
__global__ __launch_bounds__(256)
void transpose_rne(const float* __restrict__ in, float* __restrict__ out,
                   int R, int Cc, long long sIn, long long sOut)
{
    __shared__ float t[32][33];
    in  += (size_t)blockIdx.z * sIn;
    out += (size_t)blockIdx.z * sOut;
    const int tx = threadIdx.x, ty = threadIdx.y;
    const int c0 = blockIdx.x * 32, r0 = blockIdx.y * 32;
#pragma unroll
    for (int j = 0; j < 4; ++j)
        t[ty + j * 8][tx] = in[(size_t)(r0 + ty + j * 8) * Cc + c0 + tx];
    __syncthreads();
#pragma unroll
    for (int j = 0; j < 4; ++j)
        out[(size_t)(c0 + ty + j * 8) * R + r0 + tx] = rne_tf32(t[tx][ty + j * 8]);
}

__global__ __launch_bounds__(256)
void softmax_rne(float* __restrict__ S)
{
    float4* p = (float4*)(S + (size_t)blockIdx.x * NTOK);
    const int tid = threadIdx.x;
    __shared__ float red[8];
    float4 v[4];
    float mx = -3.4e38f;
#pragma unroll
    for (int j = 0; j < 4; ++j) {
        v[j] = p[tid + j * 256];
        mx = fmaxf(mx, fmaxf(fmaxf(v[j].x, v[j].y), fmaxf(v[j].z, v[j].w)));
    }
#pragma unroll
    for (int o = 16; o; o >>= 1) mx = fmaxf(mx, __shfl_xor_sync(~0u, mx, o));
    if ((tid & 31) == 0) red[tid >> 5] = mx;
    __syncthreads();
    mx = red[0];
#pragma unroll
    for (int w = 1; w < 8; ++w) mx = fmaxf(mx, red[w]);
    float sum = 0.f;
#pragma unroll
    for (int j = 0; j < 4; ++j) {
        v[j].x = __expf(v[j].x - mx); v[j].y = __expf(v[j].y - mx);
        v[j].z = __expf(v[j].z - mx); v[j].w = __expf(v[j].w - mx);
        sum += (v[j].x + v[j].y) + (v[j].z + v[j].w);
    }
#pragma unroll
    for (int o = 16; o; o >>= 1) sum += __shfl_xor_sync(~0u, sum, o);
    __syncthreads();
    if ((tid & 31) == 0) red[tid >> 5] = sum;
    __syncthreads();
    float tot = 0.f;
#pragma unroll
    for (int w = 0; w < 8; ++w) tot += red[w];
    const float inv = 1.0f / tot;
#pragma unroll
    for (int j = 0; j < 4; ++j) {
        float4 o4;
        o4.x = rne_tf32(v[j].x * inv); o4.y = rne_tf32(v[j].y * inv);
        o4.z = rne_tf32(v[j].z * inv); o4.w = rne_tf32(v[j].w * inv);
        p[tid + j * 256] = o4;
    }
}

// -------------------------------------------------------------------- launch
extern "C" void kernel_launch(void* const* d_in, const int* in_sizes, int n_in,
                              void* d_out, int out_size)
{
    const float* x  = (const float*)d_in[0];
    const float* wq = (const float*)d_in[1];
    const float* bq = (const float*)d_in[2];
    const float* wk = (const float*)d_in[3];
    const float* bk = (const float*)d_in[4];
    const float* wv = (const float*)d_in[5];
    const float* bv = (const float*)d_in[6];
    const float* wo = (const float*)d_in[7];
    const float* bo = (const float*)d_in[8];
    float* out = (float*)d_out;

    float *xt, *q, *k, *vc, *o, *s, *w;
    cudaGetSymbolAddress((void**)&xt, g_xt);
    cudaGetSymbolAddress((void**)&q,  g_q);
    cudaGetSymbolAddress((void**)&k,  g_k);
    cudaGetSymbolAddress((void**)&vc, g_vc);
    cudaGetSymbolAddress((void**)&o,  g_o);
    cudaGetSymbolAddress((void**)&s,  g_s);
    cudaGetSymbolAddress((void**)&w,  g_w);
    float* wqr = w, *wkr = w + CDIM * CDIM, *wvr = w + 2 * CDIM * CDIM, *wor = w + 3 * CDIM * CDIM;

    cudaFuncSetAttribute(gemm_mma, cudaFuncAttributeMaxDynamicSharedMemorySize, SMEM_TOTAL);

    const float scale = 0.044194173824159216f;  // 1/sqrt(512)

    weights_rne<<<CDIM * CDIM / 256, 256>>>(wq, wk, wv, wo, wqr, wkr, wvr, wor);
    transpose_rne<<<dim3(NTOK / 32, CDIM / 32, BDIM), dim3(32, 8)>>>(x, xt, CDIM, NTOK, CN, CN);

    const dim3 blk(256);
    const dim3 gP(CDIM / 256, NTOK / 128, BDIM);   // (2, 32, 2)  D = [4096, 512]
    const dim3 gS(NTOK / 256, NTOK / 128, BDIM);   // (16, 32, 2) D = [4096, 4096]
    const dim3 gY(NTOK / 256, CDIM / 128, BDIM);   // (16, 4, 2)  D = [512, 4096]

    // Q, K projections: [n, c] layouts
    gemm_mma<<<gP, blk, SMEM_TOTAL>>>(xt, wqr, q, NTOK, CDIM, CDIM, CN, 0, CN, bq, 1, scale, 1);
    gemm_mma<<<gP, blk, SMEM_TOTAL>>>(xt, wkr, k, NTOK, CDIM, CDIM, CN, 0, CN, bk, 1, 1.0f, 1);
    // V projection directly in [c, n] layout: Vc = Wv . Xt^T + bv
    gemm_mma<<<gY, blk, SMEM_TOTAL>>>(wvr, xt, vc, CDIM, NTOK, CDIM, 0, CN, CN, bv, 2, 1.0f, 1);

    // Scores + softmax
    gemm_mma<<<gS, blk, SMEM_TOTAL>>>(q, k, s, NTOK, NTOK, CDIM, CN, CN, NN, nullptr, 0, 1.0f, 0);
    softmax_rne<<<BDIM * NTOK, blk>>>(s);

    // Ot = P . Vc^T  [n, c]
    gemm_mma<<<gP, blk, SMEM_TOTAL>>>(s, vc, o, NTOK, CDIM, NTOK, NN, CN, CN, nullptr, 0, 1.0f, 1);
    // y = Wo . Ot^T + bo  [c, n]
    gemm_mma<<<gY, blk, SMEM_TOTAL>>>(wor, o, out, CDIM, NTOK, CDIM, 0, CN, CN, bo, 2, 1.0f, 0);
}

// round 14
// speedup vs baseline: 1.6259x; 1.0286x over previous
#include <cuda_runtime.h>
#include <cstdint>
#include <cstddef>

// EncoderSelfAttention, tf32 mma.sync pipeline (sm_103-safe: no tcgen05).
// B=2, C=512, N=4096.  All GEMMs K-major SS:  D[M,N] = A[M,:K] . B[N,:K]^T
//   Xt = rne(X^T)                       [n,c]
//   Qt = rne(s*(Xt.Wq^T + bq))          [n,c]
//   Kt = rne(Xt.Wk^T + bk)              [n,c]
//   Vc = rne(Wv.Xt^T + bv)              [c,n]
//   S  = Qt.Kt^T ; P = rne(softmax(S))  [n,m]
//   Ot = rne(P.Vc^T)                    [n,c]
//   y  = Wo.Ot^T + bo                   [c,n]

static constexpr int BDIM = 2, CDIM = 512, NTOK = 4096;
static constexpr long long CN = (long long)CDIM * NTOK;
static constexpr long long NN = (long long)NTOK * NTOK;

__device__ float g_xt[BDIM * NTOK * CDIM];
__device__ float g_q [BDIM * NTOK * CDIM];
__device__ float g_k [BDIM * NTOK * CDIM];
__device__ float g_vc[BDIM * CDIM * NTOK];
__device__ float g_o [BDIM * NTOK * CDIM];
__device__ float g_s [BDIM * NN];
__device__ float g_w [4][CDIM * CDIM];

// ---------------------------------------------------------------- helpers
__device__ __forceinline__ float rne_tf32(float x) {
    float r; asm("cvt.rna.tf32.f32 %0, %1;" : "=f"(r) : "f"(x)); return r;
}
__device__ __forceinline__ uint32_t smem_u32(const void* p) {
    uint32_t a;
    asm("{ .reg .u64 t; cvta.to.shared.u64 t, %1; cvt.u32.u64 %0, t; }" : "=r"(a) : "l"(p));
    return a;
}
#define CP_COMMIT() asm volatile("cp.async.commit_group;" ::: "memory")
#define CP_WAIT(n)  asm volatile("cp.async.wait_group %0;" :: "n"(n) : "memory")
__device__ __forceinline__ void cp16(uint32_t dst, const void* src) {
    asm volatile("cp.async.cg.shared.global [%0], [%1], 16;" :: "r"(dst), "l"(src) : "memory");
}
// D += A(16x8) * B(8x8)^T, tf32.
// Shared k-permutation: MMA k-slot (thread quad q, slot {q, q+4}) holds
// original k = 8q + 4p + 2ks' + {0,1}; identical for A and B -> GEMM-invariant.
__device__ __forceinline__ void mma16n8k8(float* d, float2 a_lo, float2 a_hi, float2 b) {
    asm volatile(
        "mma.sync.aligned.m16n8k8.row.col.f32.tf32.tf32.f32 "
        "{%0,%1,%2,%3},{%4,%5,%6,%7},{%8,%9},{%0,%1,%2,%3};"
        : "+f"(d[0]), "+f"(d[1]), "+f"(d[2]), "+f"(d[3])
        : "r"(__float_as_uint(a_lo.x)), "r"(__float_as_uint(a_hi.x)),
          "r"(__float_as_uint(a_lo.y)), "r"(__float_as_uint(a_hi.y)),
          "r"(__float_as_uint(b.x)),  "r"(__float_as_uint(b.y)));
}

// ---------------------------------------------------------------- GEMM
// CTA tile 128(M) x 256(N), BK=32. 8 warps = 2(M) x 4(N), warp tile 64x64.
// Smem rows: 32 floats (128B); 16B chunks XOR-swizzled by (row&7).
// Fragment loads: one LDS.128 covers two k-steps; addr over p is XOR (p<<4).
// K is a template constant so ALL cp.async addressing folds to base+immediate:
// ci and (r&7) are t-invariant (256 threads | 32 rows), so smem delta = t*4096
// and gmem delta = t*32*K, both immediates.
static constexpr int STAGES = 4;
static constexpr int A_BY = 128 * 32 * 4;           // 16 KB
static constexpr int B_BY = 256 * 32 * 4;           // 32 KB
static constexpr int STG_BY = A_BY + B_BY;          // 48 KB
static constexpr int SMEM_TOTAL = STAGES * STG_BY;  // 192 KB

template<int K>
__global__ __launch_bounds__(256, 1)
void gemm_mma(const float* __restrict__ A, const float* __restrict__ B,
              float* __restrict__ C, int N,
              long long sA, long long sB, long long sC,
              const float* __restrict__ bias, int bias_mode,  // 0 none, 1 col, 2 row
              float alpha, int do_rne)
{
    extern __shared__ char smem[];
    const uint32_t sb = smem_u32(smem);
    const int tid = threadIdx.x, wid = tid >> 5, lane = tid & 31;
    const int wm = wid >> 2, wn = wid & 3;      // warp grid 2(M) x 4(N)
    const int q = lane & 3, rg = lane >> 2;     // quad col, row-in-group
    const int bn = blockIdx.x, bm = blockIdx.y;

    A += (size_t)blockIdx.z * sA;
    B += (size_t)blockIdx.z * sB;
    C += (size_t)blockIdx.z * sC;
    const int ldc = N;

    float acc[4][8][4];
#pragma unroll
    for (int i = 0; i < 4; ++i)
#pragma unroll
        for (int j = 0; j < 8; ++j)
#pragma unroll
            for (int e = 0; e < 4; ++e) acc[i][j][e] = 0.f;

    // Fragment base byte offsets (half-chunk p=0: chunk 2q, swizzled by row).
    uint32_t aAdr[4][2], bAdr[8];
#pragma unroll
    for (int i2 = 0; i2 < 4; ++i2)
#pragma unroll
        for (int h = 0; h < 2; ++h) {
            const int r = wm * 64 + i2 * 16 + rg + h * 8;
            aAdr[i2][h] = r * 128 + ((((2 * q) ^ (r & 7))) << 4);
        }
#pragma unroll
    for (int j2 = 0; j2 < 8; ++j2) {
        const int r = wn * 64 + j2 * 8 + rg;
        bAdr[j2] = A_BY + r * 128 + ((((2 * q) ^ (r & 7))) << 4);
    }

    // Hoisted cp.async bases: per-thread row r0 = tid>>3, chunk ci = tid&7.
    // For load step t: rows advance by 32 (swizzle invariant), smem += t*4096,
    // gmem += t*32*K (immediate since K is a template constant).
    const int r0 = tid >> 3, ci = tid & 7;
    const uint32_t sOffA = (uint32_t)(r0 * 128 + ((ci ^ (r0 & 7)) << 4));
    const uint32_t sOffB = (uint32_t)A_BY + sOffA;
    const float* gA = A + (size_t)(bm * 128 + r0) * K + ci * 4;
    const float* gB = B + (size_t)(bn * 256 + r0) * K + ci * 4;

    auto load_stage = [&](int st, int k0) {
        const uint32_t base = sb + (uint32_t)st * STG_BY;
        const float* a = gA + k0;
        const float* b = gB + k0;
#pragma unroll
        for (int t = 0; t < 4; ++t)             // A: 128 rows, 32 rows per step
            cp16(base + sOffA + t * 4096u, a + (size_t)t * 32 * K);
#pragma unroll
        for (int t = 0; t < 8; ++t)             // B: 256 rows
            cp16(base + sOffB + t * 4096u, b + (size_t)t * 32 * K);
        CP_COMMIT();
    };

    const int nc = K / 32;
    load_stage(0, 0);
    load_stage(1, 32);
    load_stage(2, 64);

    for (int i = 0; i < nc; ++i) {
        CP_WAIT(2);
        __syncthreads();           // stage i ready; slot (i+3)&3 consumed at iter i-1
        if (i + 3 < nc) load_stage((i + 3) & 3, (i + 3) * 32);
        else CP_COMMIT();          // keep group counts aligned

        const uint32_t stg = (uint32_t)(i & 3) * STG_BY;
#pragma unroll
        for (int p = 0; p < 2; ++p) {           // half-chunk: two k-steps per LDS.128
            const uint32_t px = (uint32_t)p << 4;
            float4 a4[4][2], b4[8];
#pragma unroll
            for (int i2 = 0; i2 < 4; ++i2) {
                a4[i2][0] = *(const float4*)&smem[(stg + aAdr[i2][0]) ^ px];
                a4[i2][1] = *(const float4*)&smem[(stg + aAdr[i2][1]) ^ px];
            }
#pragma unroll
            for (int j2 = 0; j2 < 8; ++j2)
                b4[j2] = *(const float4*)&smem[(stg + bAdr[j2]) ^ px];
#pragma unroll
            for (int ks = 0; ks < 2; ++ks) {    // .xy then .zw
#pragma unroll
                for (int i2 = 0; i2 < 4; ++i2) {
                    const float2 alo = ks ? make_float2(a4[i2][0].z, a4[i2][0].w)
                                          : make_float2(a4[i2][0].x, a4[i2][0].y);
                    const float2 ahi = ks ? make_float2(a4[i2][1].z, a4[i2][1].w)
                                          : make_float2(a4[i2][1].x, a4[i2][1].y);
#pragma unroll
                    for (int j2 = 0; j2 < 8; ++j2) {
                        const float2 bb = ks ? make_float2(b4[j2].z, b4[j2].w)
                                             : make_float2(b4[j2].x, b4[j2].y);
                        mma16n8k8(acc[i2][j2], alo, ahi, bb);
                    }
                }
            }
        }
    }

    // Epilogue: c0,c1 -> (row, col..col+1); c2,c3 -> (row+8, col..col+1)
#pragma unroll
    for (int i2 = 0; i2 < 4; ++i2) {
#pragma unroll
        for (int j2 = 0; j2 < 8; ++j2) {
            const int row = bm * 128 + wm * 64 + i2 * 16 + rg;
            const int col = bn * 256 + wn * 64 + j2 * 8 + 2 * q;
            float b0 = 0.f, b1 = 0.f, b2 = 0.f, b3 = 0.f;
            if (bias_mode == 1) { b0 = bias[col]; b1 = bias[col + 1]; b2 = b0; b3 = b1; }
            else if (bias_mode == 2) { b0 = b1 = bias[row]; b2 = b3 = bias[row + 8]; }
            float v0 = alpha * (acc[i2][j2][0] + b0);
            float v1 = alpha * (acc[i2][j2][1] + b1);
            float v2 = alpha * (acc[i2][j2][2] + b2);
            float v3 = alpha * (acc[i2][j2][3] + b3);
            if (do_rne) { v0 = rne_tf32(v0); v1 = rne_tf32(v1); v2 = rne_tf32(v2); v3 = rne_tf32(v3); }
            *(float2*)&C[(size_t)row * ldc + col]       = make_float2(v0, v1);
            *(float2*)&C[(size_t)(row + 8) * ldc + col] = make_float2(v2, v3);
        }
    }
}

// ------------------------------------------------------- small helper kernels
__global__ __launch_bounds__(256)
void weights_rne(const float* w0, const float* w1, const float* w2, const float* w3,
                 float* o0, float* o1, float* o2, float* o3)
{
    const int i = blockIdx.x * 256 + threadIdx.x;
    o0[i] = rne_tf32(w0[i]); o1[i] = rne_tf32(w1[i]);
    o2[i] = rne_tf32(w2[i]); o3[i] = rne_tf32(w3[i]);
}

// in [R][Cc] -> out [Cc][R] with rne; grid (Cc/32, R/32, batch), block (32,8)
__global__ __launch_bounds__(256)
void transpose_rne(const float* __restrict__ in, float* __restrict__ out,
                   int R, int Cc, long long sIn, long long sOut)
{
    __shared__ float t[32][33];
    in  += (size_t)blockIdx.z * sIn;
    out += (size_t)blockIdx.z * sOut;
    const int tx = threadIdx.x, ty = threadIdx.y;
    const int c0 = blockIdx.x * 32, r0 = blockIdx.y * 32;
#pragma unroll
    for (int j = 0; j < 4; ++j)
        t[ty + j * 8][tx] = in[(size_t)(r0 + ty + j * 8) * Cc + c0 + tx];
    __syncthreads();
#pragma unroll
    for (int j = 0; j < 4; ++j)
        out[(size_t)(c0 + ty + j * 8) * R + r0 + tx] = rne_tf32(t[tx][ty + j * 8]);
}

__global__ __launch_bounds__(256)
void softmax_rne(float* __restrict__ S)
{
    float4* p = (float4*)(S + (size_t)blockIdx.x * NTOK);
    const int tid = threadIdx.x;
    __shared__ float red[8];
    float4 v[4];
    float mx = -3.4e38f;
#pragma unroll
    for (int j = 0; j < 4; ++j) {
        v[j] = p[tid + j * 256];
        mx = fmaxf(mx, fmaxf(fmaxf(v[j].x, v[j].y), fmaxf(v[j].z, v[j].w)));
    }
#pragma unroll
    for (int o = 16; o; o >>= 1) mx = fmaxf(mx, __shfl_xor_sync(~0u, mx, o));
    if ((tid & 31) == 0) red[tid >> 5] = mx;
    __syncthreads();
    mx = red[0];
#pragma unroll
    for (int w = 1; w < 8; ++w) mx = fmaxf(mx, red[w]);
    float sum = 0.f;
#pragma unroll
    for (int j = 0; j < 4; ++j) {
        v[j].x = __expf(v[j].x - mx); v[j].y = __expf(v[j].y - mx);
        v[j].z = __expf(v[j].z - mx); v[j].w = __expf(v[j].w - mx);
        sum += (v[j].x + v[j].y) + (v[j].z + v[j].w);
    }
#pragma unroll
    for (int o = 16; o; o >>= 1) sum += __shfl_xor_sync(~0u, sum, o);
    __syncthreads();
    if ((tid & 31) == 0) red[tid >> 5] = sum;
    __syncthreads();
    float tot = 0.f;
#pragma unroll
    for (int w = 0; w < 8; ++w) tot += red[w];
    const float inv = 1.0f / tot;
#pragma unroll
    for (int j = 0; j < 4; ++j) {
        float4 o4;
        o4.x = rne_tf32(v[j].x * inv); o4.y = rne_tf32(v[j].y * inv);
        o4.z = rne_tf32(v[j].z * inv); o4.w = rne_tf32(v[j].w * inv);
        p[tid + j * 256] = o4;
    }
}

// -------------------------------------------------------------------- launch
extern "C" void kernel_launch(void* const* d_in, const int* in_sizes, int n_in,
                              void* d_out, int out_size)
{
    const float* x  = (const float*)d_in[0];
    const float* wq = (const float*)d_in[1];
    const float* bq = (const float*)d_in[2];
    const float* wk = (const float*)d_in[3];
    const float* bk = (const float*)d_in[4];
    const float* wv = (const float*)d_in[5];
    const float* bv = (const float*)d_in[6];
    const float* wo = (const float*)d_in[7];
    const float* bo = (const float*)d_in[8];
    float* out = (float*)d_out;

    float *xt, *q, *k, *vc, *o, *s, *w;
    cudaGetSymbolAddress((void**)&xt, g_xt);
    cudaGetSymbolAddress((void**)&q,  g_q);
    cudaGetSymbolAddress((void**)&k,  g_k);
    cudaGetSymbolAddress((void**)&vc, g_vc);
    cudaGetSymbolAddress((void**)&o,  g_o);
    cudaGetSymbolAddress((void**)&s,  g_s);
    cudaGetSymbolAddress((void**)&w,  g_w);
    float* wqr = w, *wkr = w + CDIM * CDIM, *wvr = w + 2 * CDIM * CDIM, *wor = w + 3 * CDIM * CDIM;

    cudaFuncSetAttribute(gemm_mma<512>,  cudaFuncAttributeMaxDynamicSharedMemorySize, SMEM_TOTAL);
    cudaFuncSetAttribute(gemm_mma<4096>, cudaFuncAttributeMaxDynamicSharedMemorySize, SMEM_TOTAL);

    const float scale = 0.044194173824159216f;  // 1/sqrt(512)

    weights_rne<<<CDIM * CDIM / 256, 256>>>(wq, wk, wv, wo, wqr, wkr, wvr, wor);
    transpose_rne<<<dim3(NTOK / 32, CDIM / 32, BDIM), dim3(32, 8)>>>(x, xt, CDIM, NTOK, CN, CN);

    const dim3 blk(256);
    const dim3 gP(CDIM / 256, NTOK / 128, BDIM);   // (2, 32, 2)  D = [4096, 512]
    const dim3 gS(NTOK / 256, NTOK / 128, BDIM);   // (16, 32, 2) D = [4096, 4096]
    const dim3 gY(NTOK / 256, CDIM / 128, BDIM);   // (16, 4, 2)  D = [512, 4096]

    // Q, K projections: [n, c] layouts
    gemm_mma<512><<<gP, blk, SMEM_TOTAL>>>(xt, wqr, q, CDIM, CN, 0, CN, bq, 1, scale, 1);
    gemm_mma<512><<<gP, blk, SMEM_TOTAL>>>(xt, wkr, k, CDIM, CN, 0, CN, bk, 1, 1.0f, 1);
    // V projection directly in [c, n] layout: Vc = Wv . Xt^T + bv
    gemm_mma<512><<<gY, blk, SMEM_TOTAL>>>(wvr, xt, vc, NTOK, 0, CN, CN, bv, 2, 1.0f, 1);

    // Scores + softmax
    gemm_mma<512><<<gS, blk, SMEM_TOTAL>>>(q, k, s, NTOK, CN, CN, NN, nullptr, 0, 1.0f, 0);
    softmax_rne<<<BDIM * NTOK, blk>>>(s);

    // Ot = P . Vc^T  [n, c]
    gemm_mma<4096><<<gP, blk, SMEM_TOTAL>>>(s, vc, o, CDIM, NN, CN, CN, nullptr, 0, 1.0f, 1);
    // y = Wo . Ot^T + bo  [c, n]
    gemm_mma<512><<<gY, blk, SMEM_TOTAL>>>(wor, o, out, NTOK, 0, CN, CN, bo, 2, 1.0f, 0);
}

// round 15
// speedup vs baseline: 1.6909x; 1.0400x over previous
#include <cuda_runtime.h>
#include <cstdint>
#include <cstddef>

// EncoderSelfAttention, tf32 mma.sync pipeline (sm_103-safe: no tcgen05).
// B=2, C=512, N=4096.  All GEMMs K-major SS:  D[M,N] = A[M,:K] . B[N,:K]^T
//   Xt = rne(X^T)                       [n,c]
//   Qt = rne(s*(Xt.Wq^T + bq))          [n,c]
//   Kt = rne(Xt.Wk^T + bk)              [n,c]
//   Vc = rne(Wv.Xt^T + bv)              [c,n]
//   S  = Qt.Kt^T ; P = rne(softmax(S))  [n,m]
//   Ot = rne(P.Vc^T)                    [n,c]
//   y  = Wo.Ot^T + bo                   [c,n]

static constexpr int BDIM = 2, CDIM = 512, NTOK = 4096;
static constexpr long long CN = (long long)CDIM * NTOK;
static constexpr long long NN = (long long)NTOK * NTOK;

__device__ float g_xt[BDIM * NTOK * CDIM];
__device__ float g_q [BDIM * NTOK * CDIM];
__device__ float g_k [BDIM * NTOK * CDIM];
__device__ float g_vc[BDIM * CDIM * NTOK];
__device__ float g_o [BDIM * NTOK * CDIM];
__device__ float g_s [BDIM * NN];
__device__ float g_w [4][CDIM * CDIM];

// ---------------------------------------------------------------- helpers
__device__ __forceinline__ float rne_tf32(float x) {
    float r; asm("cvt.rna.tf32.f32 %0, %1;" : "=f"(r) : "f"(x)); return r;
}
__device__ __forceinline__ uint32_t smem_u32(const void* p) {
    uint32_t a;
    asm("{ .reg .u64 t; cvta.to.shared.u64 t, %1; cvt.u32.u64 %0, t; }" : "=r"(a) : "l"(p));
    return a;
}
#define CP_COMMIT() asm volatile("cp.async.commit_group;" ::: "memory")
#define CP_WAIT(n)  asm volatile("cp.async.wait_group %0;" :: "n"(n) : "memory")
__device__ __forceinline__ void cp16(uint32_t dst, const void* src) {
    asm volatile("cp.async.cg.shared.global [%0], [%1], 16;" :: "r"(dst), "l"(src) : "memory");
}
// D += A(16x8) * B(8x8)^T, tf32.
// Shared k-permutation: MMA k-slot (thread quad q, slot {q, q+4}) holds
// original k = 8q + 4p + 2ks' + {0,1}; identical for A and B -> GEMM-invariant.
__device__ __forceinline__ void mma16n8k8(float* d, float2 a_lo, float2 a_hi, float2 b) {
    asm volatile(
        "mma.sync.aligned.m16n8k8.row.col.f32.tf32.tf32.f32 "
        "{%0,%1,%2,%3},{%4,%5,%6,%7},{%8,%9},{%0,%1,%2,%3};"
        : "+f"(d[0]), "+f"(d[1]), "+f"(d[2]), "+f"(d[3])
        : "r"(__float_as_uint(a_lo.x)), "r"(__float_as_uint(a_hi.x)),
          "r"(__float_as_uint(a_lo.y)), "r"(__float_as_uint(a_hi.y)),
          "r"(__float_as_uint(b.x)),  "r"(__float_as_uint(b.y)));
}

// ---------------------------------------------------------------- GEMM
// CTA tile 128(M) x 128(N), BK=32, 128 threads: 4 warps = 2(M) x 2(N),
// warp tile 64x64. 3 smem stages x 32KB = 96KB -> 2 CTAs resident per SM
// (barrier/latency stalls of one CTA are covered by the other).
// Smem rows: 32 floats (128B); 16B chunks XOR-swizzled by (row&7).
// One LDS.128 covers two k-steps; fragment addr over p advances by XOR (p<<4).
static constexpr int STAGES = 3;
static constexpr int A_BY = 128 * 32 * 4;           // 16 KB
static constexpr int B_BY = 128 * 32 * 4;           // 16 KB
static constexpr int STG_BY = A_BY + B_BY;          // 32 KB
static constexpr int SMEM_TOTAL = STAGES * STG_BY;  // 96 KB

template<int K>
__global__ __launch_bounds__(128, 2)
void gemm_mma(const float* __restrict__ A, const float* __restrict__ B,
              float* __restrict__ C, int N,
              long long sA, long long sB, long long sC,
              const float* __restrict__ bias, int bias_mode,  // 0 none, 1 col, 2 row
              float alpha, int do_rne)
{
    extern __shared__ char smem[];
    const uint32_t sb = smem_u32(smem);
    const int tid = threadIdx.x, wid = tid >> 5, lane = tid & 31;
    const int wm = wid >> 1, wn = wid & 1;      // warp grid 2(M) x 2(N)
    const int q = lane & 3, rg = lane >> 2;     // quad col, row-in-group
    const int bn = blockIdx.x, bm = blockIdx.y;

    A += (size_t)blockIdx.z * sA;
    B += (size_t)blockIdx.z * sB;
    C += (size_t)blockIdx.z * sC;
    const int ldc = N;

    float acc[4][8][4];
#pragma unroll
    for (int i = 0; i < 4; ++i)
#pragma unroll
        for (int j = 0; j < 8; ++j)
#pragma unroll
            for (int e = 0; e < 4; ++e) acc[i][j][e] = 0.f;

    // Fragment base byte offsets (half-chunk p=0: chunk 2q, swizzled by row).
    uint32_t aAdr[4][2], bAdr[8];
#pragma unroll
    for (int i2 = 0; i2 < 4; ++i2)
#pragma unroll
        for (int h = 0; h < 2; ++h) {
            const int r = wm * 64 + i2 * 16 + rg + h * 8;
            aAdr[i2][h] = r * 128 + ((((2 * q) ^ (r & 7))) << 4);
        }
#pragma unroll
    for (int j2 = 0; j2 < 8; ++j2) {
        const int r = wn * 64 + j2 * 8 + rg;
        bAdr[j2] = A_BY + r * 128 + ((((2 * q) ^ (r & 7))) << 4);
    }

    // Hoisted cp.async bases: r0 = tid>>3 (0..15), ci = tid&7.
    // Step t covers rows r0 + 16t (16 = multiple of 8 -> swizzle invariant):
    // smem += t*2048, gmem += t*16*K (immediates; K is a template constant).
    const int r0 = tid >> 3, ci = tid & 7;
    const uint32_t sOffA = (uint32_t)(r0 * 128 + ((ci ^ (r0 & 7)) << 4));
    const uint32_t sOffB = (uint32_t)A_BY + sOffA;
    const float* gA = A + (size_t)(bm * 128 + r0) * K + ci * 4;
    const float* gB = B + (size_t)(bn * 128 + r0) * K + ci * 4;

    auto load_stage = [&](int st, int k0) {
        const uint32_t base = sb + (uint32_t)st * STG_BY;
        const float* a = gA + k0;
        const float* b = gB + k0;
#pragma unroll
        for (int t = 0; t < 8; ++t)             // A: 128 rows, 16 rows per step
            cp16(base + sOffA + t * 2048u, a + (size_t)t * 16 * K);
#pragma unroll
        for (int t = 0; t < 8; ++t)             // B: 128 rows
            cp16(base + sOffB + t * 2048u, b + (size_t)t * 16 * K);
        CP_COMMIT();
    };

    const int nc = K / 32;
    load_stage(0, 0);
    load_stage(1, 32);

    int cst = 0, lst = 2;                       // compute / next-load stage ids
    for (int i = 0; i < nc; ++i) {
        CP_WAIT(1);
        __syncthreads();           // stage i ready; slot lst consumed in iter i-1
        if (i + 2 < nc) {
            load_stage(lst, (i + 2) * 32);
            if (++lst == STAGES) lst = 0;
        } else {
            CP_COMMIT();           // keep group counts aligned
        }

        const uint32_t stg = (uint32_t)cst * STG_BY;
        if (++cst == STAGES) cst = 0;
#pragma unroll
        for (int p = 0; p < 2; ++p) {           // half-chunk: two k-steps per LDS.128
            const uint32_t px = (uint32_t)p << 4;
            float4 a4[4][2], b4[8];
#pragma unroll
            for (int i2 = 0; i2 < 4; ++i2) {
                a4[i2][0] = *(const float4*)&smem[(stg + aAdr[i2][0]) ^ px];
                a4[i2][1] = *(const float4*)&smem[(stg + aAdr[i2][1]) ^ px];
            }
#pragma unroll
            for (int j2 = 0; j2 < 8; ++j2)
                b4[j2] = *(const float4*)&smem[(stg + bAdr[j2]) ^ px];
#pragma unroll
            for (int ks = 0; ks < 2; ++ks) {    // .xy then .zw
#pragma unroll
                for (int i2 = 0; i2 < 4; ++i2) {
                    const float2 alo = ks ? make_float2(a4[i2][0].z, a4[i2][0].w)
                                          : make_float2(a4[i2][0].x, a4[i2][0].y);
                    const float2 ahi = ks ? make_float2(a4[i2][1].z, a4[i2][1].w)
                                          : make_float2(a4[i2][1].x, a4[i2][1].y);
#pragma unroll
                    for (int j2 = 0; j2 < 8; ++j2) {
                        const float2 bb = ks ? make_float2(b4[j2].z, b4[j2].w)
                                             : make_float2(b4[j2].x, b4[j2].y);
                        mma16n8k8(acc[i2][j2], alo, ahi, bb);
                    }
                }
            }
        }
    }

    // Epilogue: c0,c1 -> (row, col..col+1); c2,c3 -> (row+8, col..col+1)
#pragma unroll
    for (int i2 = 0; i2 < 4; ++i2) {
#pragma unroll
        for (int j2 = 0; j2 < 8; ++j2) {
            const int row = bm * 128 + wm * 64 + i2 * 16 + rg;
            const int col = bn * 128 + wn * 64 + j2 * 8 + 2 * q;
            float b0 = 0.f, b1 = 0.f, b2 = 0.f, b3 = 0.f;
            if (bias_mode == 1) { b0 = bias[col]; b1 = bias[col + 1]; b2 = b0; b3 = b1; }
            else if (bias_mode == 2) { b0 = b1 = bias[row]; b2 = b3 = bias[row + 8]; }
            float v0 = alpha * (acc[i2][j2][0] + b0);
            float v1 = alpha * (acc[i2][j2][1] + b1);
            float v2 = alpha * (acc[i2][j2][2] + b2);
            float v3 = alpha * (acc[i2][j2][3] + b3);
            if (do_rne) { v0 = rne_tf32(v0); v1 = rne_tf32(v1); v2 = rne_tf32(v2); v3 = rne_tf32(v3); }
            *(float2*)&C[(size_t)row * ldc + col]       = make_float2(v0, v1);
            *(float2*)&C[(size_t)(row + 8) * ldc + col] = make_float2(v2, v3);
        }
    }
}

// ------------------------------------------------------- small helper kernels
__global__ __launch_bounds__(256)
void weights_rne(const float* w0, const float* w1, const float* w2, const float* w3,
                 float* o0, float* o1, float* o2, float* o3)
{
    const int i = blockIdx.x * 256 + threadIdx.x;
    o0[i] = rne_tf32(w0[i]); o1[i] = rne_tf32(w1[i]);
    o2[i] = rne_tf32(w2[i]); o3[i] = rne_tf32(w3[i]);
}

// in [R][Cc] -> out [Cc][R] with rne; grid (Cc/32, R/32, batch), block (32,8)
__global__ __launch_bounds__(256)
void transpose_rne(const float* __restrict__ in, float* __restrict__ out,
                   int R, int Cc, long long sIn, long long sOut)
{
    __shared__ float t[32][33];
    in  += (size_t)blockIdx.z * sIn;
    out += (size_t)blockIdx.z * sOut;
    const int tx = threadIdx.x, ty = threadIdx.y;
    const int c0 = blockIdx.x * 32, r0 = blockIdx.y * 32;
#pragma unroll
    for (int j = 0; j < 4; ++j)
        t[ty + j * 8][tx] = in[(size_t)(r0 + ty + j * 8) * Cc + c0 + tx];
    __syncthreads();
#pragma unroll
    for (int j = 0; j < 4; ++j)
        out[(size_t)(c0 + ty + j * 8) * R + r0 + tx] = rne_tf32(t[tx][ty + j * 8]);
}

__global__ __launch_bounds__(256)
void softmax_rne(float* __restrict__ S)
{
    float4* p = (float4*)(S + (size_t)blockIdx.x * NTOK);
    const int tid = threadIdx.x;
    __shared__ float red[8];
    float4 v[4];
    float mx = -3.4e38f;
#pragma unroll
    for (int j = 0; j < 4; ++j) {
        v[j] = p[tid + j * 256];
        mx = fmaxf(mx, fmaxf(fmaxf(v[j].x, v[j].y), fmaxf(v[j].z, v[j].w)));
    }
#pragma unroll
    for (int o = 16; o; o >>= 1) mx = fmaxf(mx, __shfl_xor_sync(~0u, mx, o));
    if ((tid & 31) == 0) red[tid >> 5] = mx;
    __syncthreads();
    mx = red[0];
#pragma unroll
    for (int w = 1; w < 8; ++w) mx = fmaxf(mx, red[w]);
    float sum = 0.f;
#pragma unroll
    for (int j = 0; j < 4; ++j) {
        v[j].x = __expf(v[j].x - mx); v[j].y = __expf(v[j].y - mx);
        v[j].z = __expf(v[j].z - mx); v[j].w = __expf(v[j].w - mx);
        sum += (v[j].x + v[j].y) + (v[j].z + v[j].w);
    }
#pragma unroll
    for (int o = 16; o; o >>= 1) sum += __shfl_xor_sync(~0u, sum, o);
    __syncthreads();
    if ((tid & 31) == 0) red[tid >> 5] = sum;
    __syncthreads();
    float tot = 0.f;
#pragma unroll
    for (int w = 0; w < 8; ++w) tot += red[w];
    const float inv = 1.0f / tot;
#pragma unroll
    for (int j = 0; j < 4; ++j) {
        float4 o4;
        o4.x = rne_tf32(v[j].x * inv); o4.y = rne_tf32(v[j].y * inv);
        o4.z = rne_tf32(v[j].z * inv); o4.w = rne_tf32(v[j].w * inv);
        p[tid + j * 256] = o4;
    }
}

// -------------------------------------------------------------------- launch
extern "C" void kernel_launch(void* const* d_in, const int* in_sizes, int n_in,
                              void* d_out, int out_size)
{
    const float* x  = (const float*)d_in[0];
    const float* wq = (const float*)d_in[1];
    const float* bq = (const float*)d_in[2];
    const float* wk = (const float*)d_in[3];
    const float* bk = (const float*)d_in[4];
    const float* wv = (const float*)d_in[5];
    const float* bv = (const float*)d_in[6];
    const float* wo = (const float*)d_in[7];
    const float* bo = (const float*)d_in[8];
    float* out = (float*)d_out;

    float *xt, *q, *k, *vc, *o, *s, *w;
    cudaGetSymbolAddress((void**)&xt, g_xt);
    cudaGetSymbolAddress((void**)&q,  g_q);
    cudaGetSymbolAddress((void**)&k,  g_k);
    cudaGetSymbolAddress((void**)&vc, g_vc);
    cudaGetSymbolAddress((void**)&o,  g_o);
    cudaGetSymbolAddress((void**)&s,  g_s);
    cudaGetSymbolAddress((void**)&w,  g_w);
    float* wqr = w, *wkr = w + CDIM * CDIM, *wvr = w + 2 * CDIM * CDIM, *wor = w + 3 * CDIM * CDIM;

    cudaFuncSetAttribute(gemm_mma<512>,  cudaFuncAttributeMaxDynamicSharedMemorySize, SMEM_TOTAL);
    cudaFuncSetAttribute(gemm_mma<4096>, cudaFuncAttributeMaxDynamicSharedMemorySize, SMEM_TOTAL);

    const float scale = 0.044194173824159216f;  // 1/sqrt(512)

    weights_rne<<<CDIM * CDIM / 256, 256>>>(wq, wk, wv, wo, wqr, wkr, wvr, wor);
    transpose_rne<<<dim3(NTOK / 32, CDIM / 32, BDIM), dim3(32, 8)>>>(x, xt, CDIM, NTOK, CN, CN);

    const dim3 blk(128);
    const dim3 gP(CDIM / 128, NTOK / 128, BDIM);   // (4, 32, 2)  D = [4096, 512]
    const dim3 gS(NTOK / 128, NTOK / 128, BDIM);   // (32, 32, 2) D = [4096, 4096]
    const dim3 gY(NTOK / 128, CDIM / 128, BDIM);   // (32, 4, 2)  D = [512, 4096]

    // Q, K projections: [n, c] layouts
    gemm_mma<512><<<gP, blk, SMEM_TOTAL>>>(xt, wqr, q, CDIM, CN, 0, CN, bq, 1, scale, 1);
    gemm_mma<512><<<gP, blk, SMEM_TOTAL>>>(xt, wkr, k, CDIM, CN, 0, CN, bk, 1, 1.0f, 1);
    // V projection directly in [c, n] layout: Vc = Wv . Xt^T + bv
    gemm_mma<512><<<gY, blk, SMEM_TOTAL>>>(wvr, xt, vc, NTOK, 0, CN, CN, bv, 2, 1.0f, 1);

    // Scores + softmax
    gemm_mma<512><<<gS, blk, SMEM_TOTAL>>>(q, k, s, NTOK, CN, CN, NN, nullptr, 0, 1.0f, 0);
    softmax_rne<<<BDIM * NTOK, 256>>>(s);

    // Ot = P . Vc^T  [n, c]
    gemm_mma<4096><<<gP, blk, SMEM_TOTAL>>>(s, vc, o, CDIM, NN, CN, CN, nullptr, 0, 1.0f, 1);
    // y = Wo . Ot^T + bo  [c, n]
    gemm_mma<512><<<gY, blk, SMEM_TOTAL>>>(wor, o, out, NTOK, 0, CN, CN, bo, 2, 1.0f, 0);
}